// round 2
// baseline (speedup 1.0000x reference)
#include <cuda_runtime.h>
#include <cuda_bf16.h>
#include <math.h>

// Problem constants
#define BB   16
#define N1   1024
#define N2   4096
#define CF   512      // C_IN == C_OUT == 512
#define EPSI 1e-10f

// Scratch (device globals; no dynamic allocation allowed)
__device__ float g_gbuf[BB * N1 * CF];   // feat_sparse @ W1^T + b1      (16384 x 512)
__device__ float hi_gbuf[BB * N2 * CF];  // relu(interp(g))              (65536 x 512)

// ---------------------------------------------------------------------------
// SGEMM:  C[M,N] = A[M,K] * W[N,K]^T + bias[N]
// 128x128 tile, BK=8, 256 threads, 8x8 per-thread register tile.
// MODE 0: A = param,  C = g_gbuf   (GEMM1)
// MODE 1: A = hi_gbuf, C = param   (GEMM2)
// (avoids any host-side symbol-address query in kernel_launch)
// ---------------------------------------------------------------------------
template <int MODE>
__global__ __launch_bounds__(256, 2) void sgemm_bias_kernel(
    const float* __restrict__ Ain, const float* __restrict__ W,
    const float* __restrict__ bias, float* __restrict__ Cout,
    int M, int N, int K)
{
    const float* A = (MODE == 1) ? (const float*)hi_gbuf : Ain;
    float*       C = (MODE == 0) ? (float*)g_gbuf        : Cout;

    __shared__ float As[8][128];
    __shared__ float Bs[8][128];

    const int tid  = threadIdx.x;
    const int tx   = tid & 15;        // 0..15  -> 8 cols each
    const int ty   = tid >> 4;        // 0..15  -> 8 rows each
    const int row0 = blockIdx.y * 128;
    const int col0 = blockIdx.x * 128;

    const int lrow  = tid >> 1;       // 0..127
    const int lcol4 = (tid & 1) * 4;  // 0 or 4

    float acc[8][8];
#pragma unroll
    for (int i = 0; i < 8; i++)
#pragma unroll
        for (int j = 0; j < 8; j++) acc[i][j] = 0.f;

    const float* Aptr = A + (long)(row0 + lrow) * K + lcol4;
    const float* Wptr = W + (long)(col0 + lrow) * K + lcol4;

    for (int k0 = 0; k0 < K; k0 += 8) {
        float4 av = *(const float4*)(Aptr + k0);
        float4 wv = *(const float4*)(Wptr + k0);
        As[lcol4 + 0][lrow] = av.x;
        As[lcol4 + 1][lrow] = av.y;
        As[lcol4 + 2][lrow] = av.z;
        As[lcol4 + 3][lrow] = av.w;
        Bs[lcol4 + 0][lrow] = wv.x;
        Bs[lcol4 + 1][lrow] = wv.y;
        Bs[lcol4 + 2][lrow] = wv.z;
        Bs[lcol4 + 3][lrow] = wv.w;
        __syncthreads();

#pragma unroll
        for (int k = 0; k < 8; k++) {
            float ar[8], br[8];
#pragma unroll
            for (int i = 0; i < 8; i++) ar[i] = As[k][ty * 8 + i];
#pragma unroll
            for (int j = 0; j < 8; j++) br[j] = Bs[k][tx * 8 + j];
#pragma unroll
            for (int i = 0; i < 8; i++)
#pragma unroll
                for (int j = 0; j < 8; j++)
                    acc[i][j] = fmaf(ar[i], br[j], acc[i][j]);
        }
        __syncthreads();
    }

    // Epilogue: +bias, float4 stores
    float4 bv0 = *(const float4*)&bias[col0 + tx * 8 + 0];
    float4 bv1 = *(const float4*)&bias[col0 + tx * 8 + 4];
#pragma unroll
    for (int i = 0; i < 8; i++) {
        const int row = row0 + ty * 8 + i;
        float4 o0, o1;
        o0.x = acc[i][0] + bv0.x; o0.y = acc[i][1] + bv0.y;
        o0.z = acc[i][2] + bv0.z; o0.w = acc[i][3] + bv0.w;
        o1.x = acc[i][4] + bv1.x; o1.y = acc[i][5] + bv1.y;
        o1.z = acc[i][6] + bv1.z; o1.w = acc[i][7] + bv1.w;
        *(float4*)&C[(long)row * N + col0 + tx * 8 + 0] = o0;
        *(float4*)&C[(long)row * N + col0 + tx * 8 + 4] = o1;
    }
}

// ---------------------------------------------------------------------------
// KNN(3) + inverse-distance-weighted interpolation of g, fused with ReLU.
// One block = 128 dense points of one batch. 256 threads.
//   phase 1: threads 0..127 each scan all 1024 sparse points -> top-3 + weights
//   phase 2: all 256 threads do the weighted 3-row gather over 512 channels
// ---------------------------------------------------------------------------
__global__ __launch_bounds__(256) void knn_interp_relu_kernel(
    const float* __restrict__ xyz_dense, const float* __restrict__ xyz_sparse)
{
    __shared__ float sx[N1], sy[N1], sz[N1];
    __shared__ float sw[128][3];
    __shared__ int   si[128][3];

    const int b  = blockIdx.y;
    const int p0 = blockIdx.x * 128;

    // stage sparse xyz of this batch
    const float* xs = xyz_sparse + (long)b * N1 * 3;
    for (int i = threadIdx.x; i < N1; i += 256) {
        sx[i] = xs[i * 3 + 0];
        sy[i] = xs[i * 3 + 1];
        sz[i] = xs[i * 3 + 2];
    }
    __syncthreads();

    if (threadIdx.x < 128) {
        const int p = p0 + threadIdx.x;
        const float* xd = xyz_dense + ((long)b * N2 + p) * 3;
        const float px = xd[0], py = xd[1], pz = xd[2];

        float d0 = 1e30f, d1 = 1e30f, d2 = 1e30f;
        int   i0 = 0,     i1 = 0,     i2 = 0;
#pragma unroll 4
        for (int j = 0; j < N1; j++) {
            float dx = px - sx[j];
            float dy = py - sy[j];
            float dz = pz - sz[j];
            float d  = dx * dx + dy * dy + dz * dz;
            if (d < d0)      { d2 = d1; i2 = i1; d1 = d0; i1 = i0; d0 = d; i0 = j; }
            else if (d < d1) { d2 = d1; i2 = i1; d1 = d;  i1 = j; }
            else if (d < d2) { d2 = d;  i2 = j; }
        }
        float w0 = 1.f / (sqrtf(d0) + EPSI);
        float w1 = 1.f / (sqrtf(d1) + EPSI);
        float w2 = 1.f / (sqrtf(d2) + EPSI);
        const float inv = 1.f / (w0 + w1 + w2);
        sw[threadIdx.x][0] = w0 * inv;
        sw[threadIdx.x][1] = w1 * inv;
        sw[threadIdx.x][2] = w2 * inv;
        si[threadIdx.x][0] = i0;
        si[threadIdx.x][1] = i1;
        si[threadIdx.x][2] = i2;
    }
    __syncthreads();

    const float* g  = g_gbuf  + (long)b * N1 * CF;
    float*       hi = hi_gbuf + ((long)b * N2 + p0) * CF;

    for (int e = threadIdx.x; e < 128 * CF; e += 256) {
        const int p = e >> 9;       // point within block
        const int c = e & (CF - 1); // channel
        const float v = sw[p][0] * g[(long)si[p][0] * CF + c]
                      + sw[p][1] * g[(long)si[p][1] * CF + c]
                      + sw[p][2] * g[(long)si[p][2] * CF + c];
        hi[(long)p * CF + c] = fmaxf(v, 0.f);
    }
}

// ---------------------------------------------------------------------------
// Launch
// ---------------------------------------------------------------------------
extern "C" void kernel_launch(void* const* d_in, const int* in_sizes, int n_in,
                              void* d_out, int out_size)
{
    const float* xyz_dense  = (const float*)d_in[0];  // (16, 4096, 3)
    const float* xyz_sparse = (const float*)d_in[1];  // (16, 1024, 3)
    const float* feat       = (const float*)d_in[2];  // (16, 1024, 512)
    const float* W1         = (const float*)d_in[3];  // (512, 512)
    const float* b1         = (const float*)d_in[4];  // (512)
    const float* W2         = (const float*)d_in[5];  // (512, 512)
    const float* b2         = (const float*)d_in[6];  // (512)
    float* out = (float*)d_out;                       // (16, 4096, 512)

    // 1) g = feat_sparse @ W1^T + b1   (16384 x 512), using linearity of the
    //    interpolation: interp(feat) @ W1 + b1 == interp(feat @ W1 + b1)
    {
        dim3 grid(CF / 128, (BB * N1) / 128);  // (4, 128)
        sgemm_bias_kernel<0><<<grid, 256>>>(feat, W1, b1, nullptr, BB * N1, CF, CF);
    }

    // 2) hi = relu(interp3(g))   (65536 x 512)
    {
        dim3 grid(N2 / 128, BB);               // (32, 16)
        knn_interp_relu_kernel<<<grid, 256>>>(xyz_dense, xyz_sparse);
    }

    // 3) out = hi @ W2^T + b2   (65536 x 512)
    {
        dim3 grid(CF / 128, (BB * N2) / 128);  // (4, 512)
        sgemm_bias_kernel<1><<<grid, 256>>>(nullptr, W2, b2, out, BB * N2, CF, CF);
    }
}

// round 4
// speedup vs baseline: 2.1470x; 2.1470x over previous
#include <cuda_runtime.h>
#include <cuda_bf16.h>
#include <math.h>
#include <stdint.h>

// ---------------------------------------------------------------- constants
#define BB    16
#define NPTS1 1024
#define NPTS2 4096
#define CF    512
#define EPSI  1e-10f

#define MTILES1 128            // 16384/128
#define MTILES2 512            // 65536/128
#define KITERS  16             // 512 / BK32

// SMEM tile geometry: per matrix 128 rows x 32 bf16 (64B data, padded to 80B)
#define ROW_STRIDE 80
#define MAT_BYTES  (128 * ROW_STRIDE)      // 10240
#define STAGE_BYTES (4 * MAT_BYTES)        // 40960 (Ahi|Alo|Bhi|Blo)
#define SMEM_GEMM   (2 * STAGE_BYTES)      // 81920

// ---------------------------------------------------------------- scratch
// Row-major bf16 hi/lo splits (x = hi + lo; hi=bf16(x), lo=bf16(x-hi))
__device__ __align__(128) __nv_bfloat16 g_fA_hi[16384 * 512];
__device__ __align__(128) __nv_bfloat16 g_fA_lo[16384 * 512];
__device__ __align__(128) __nv_bfloat16 g_w1_hi[512 * 512];
__device__ __align__(128) __nv_bfloat16 g_w1_lo[512 * 512];
__device__ __align__(128) __nv_bfloat16 g_w2_hi[512 * 512];
__device__ __align__(128) __nv_bfloat16 g_w2_lo[512 * 512];
__device__ __align__(128) __nv_bfloat16 g_a2_hi[65536 * 512];
__device__ __align__(128) __nv_bfloat16 g_a2_lo[65536 * 512];
__device__ float g_gbuf[16384 * 512];   // GEMM1 output (fp32)

// ---------------------------------------------------------------- helpers
__device__ __forceinline__ uint32_t smem_u32(const void* p) {
    uint32_t a;
    asm("{ .reg .u64 t; cvta.to.shared.u64 t, %1; cvt.u32.u64 %0, t; }"
        : "=r"(a) : "l"(p));
    return a;
}

__device__ __forceinline__ void cp16(uint32_t dst, const void* src) {
    asm volatile("cp.async.cg.shared.global [%0], [%1], 16;" :: "r"(dst), "l"(src));
}

#define CP_COMMIT()  asm volatile("cp.async.commit_group;" ::: "memory")
#define CP_WAIT1()   asm volatile("cp.async.wait_group 1;" ::: "memory")
#define CP_WAIT0()   asm volatile("cp.async.wait_group 0;" ::: "memory")

// D += A(16x16 bf16, row-major) * B(16x8 bf16, col-major), fp32 accum
#define MMA_BF16(d, a, b0_, b1_)                                              \
    asm volatile("mma.sync.aligned.m16n8k16.row.col.f32.bf16.bf16.f32 "       \
        "{%0,%1,%2,%3}, {%4,%5,%6,%7}, {%8,%9}, {%0,%1,%2,%3};"               \
        : "+f"((d)[0]), "+f"((d)[1]), "+f"((d)[2]), "+f"((d)[3])              \
        : "r"((a)[0]), "r"((a)[1]), "r"((a)[2]), "r"((a)[3]),                 \
          "r"(b0_), "r"(b1_))

// ---------------------------------------------------------------- converters
// src: (M x 512) fp32 row-major -> row-major bf16 hi/lo (same layout)
template <int WHICH>  // 0: feat->fA   1: W1->w1   2: W2->w2
__global__ __launch_bounds__(256) void convert_split_kernel(const float* __restrict__ src)
{
    __nv_bfloat16* dhi = (WHICH == 0) ? g_fA_hi : (WHICH == 1) ? g_w1_hi : g_w2_hi;
    __nv_bfloat16* dlo = (WHICH == 0) ? g_fA_lo : (WHICH == 1) ? g_w1_lo : g_w2_lo;

    const long t = (long)blockIdx.x * 256 + threadIdx.x;   // one 8-elem chunk
    const float4* s = (const float4*)(src + t * 8);
    float4 v0 = s[0], v1 = s[1];
    float v[8] = { v0.x, v0.y, v0.z, v0.w, v1.x, v1.y, v1.z, v1.w };

    union { __nv_bfloat16 h[8]; uint4 u; } H, L;
#pragma unroll
    for (int k = 0; k < 8; k++) {
        H.h[k] = __float2bfloat16(v[k]);
        L.h[k] = __float2bfloat16(v[k] - __bfloat162float(H.h[k]));
    }
    *(uint4*)(dhi + t * 8) = H.u;
    *(uint4*)(dlo + t * 8) = L.u;
}

// ---------------------------------------------------------------- MMA GEMM
// C[M,512] = A[M,512] @ W[512,512]^T + bias, 3-term bf16 split:
//   AhiBhi + AhiBlo + AloBhi  (AloBlo dropped, ~2^-18)
// MODE 0: A = fA (feat), B = w1, C = g_gbuf.  MODE 1: A = a2, B = w2, C = param.
template <int MODE>
__global__ __launch_bounds__(256, 1) void mma_gemm_kernel(const float* __restrict__ bias,
                                                          float* __restrict__ Cout)
{
    extern __shared__ __align__(128) char smem[];
    const uint32_t sbase = smem_u32(smem);

    const int tid  = threadIdx.x;
    const int wid  = tid >> 5, lane = tid & 31;
    const int warp_m = wid & 3;     // 0..3 -> 32-row strip
    const int warp_n = wid >> 2;    // 0..1 -> 64-col strip
    const int qid = lane >> 2;      // t/4
    const int qtr = lane & 3;       // t%4
    const int ntile = blockIdx.x, mtile = blockIdx.y;

    const __nv_bfloat16* Ahi = (MODE == 0) ? g_fA_hi : g_a2_hi;
    const __nv_bfloat16* Alo = (MODE == 0) ? g_fA_lo : g_a2_lo;
    const __nv_bfloat16* Bhi = (MODE == 0) ? g_w1_hi : g_w2_hi;
    const __nv_bfloat16* Blo = (MODE == 0) ? g_w1_lo : g_w2_lo;

    // global tile bases (bytes): row-major, 512 bf16 = 1024B per row
    const char* gbase[4];
    gbase[0] = (const char*)(Ahi + (long)mtile * 128 * 512);
    gbase[1] = (const char*)(Alo + (long)mtile * 128 * 512);
    gbase[2] = (const char*)(Bhi + (long)ntile * 128 * 512);
    gbase[3] = (const char*)(Blo + (long)ntile * 128 * 512);

    float acc[2][8][4];
#pragma unroll
    for (int mt = 0; mt < 2; mt++)
#pragma unroll
        for (int nt = 0; nt < 8; nt++)
#pragma unroll
            for (int i = 0; i < 4; i++) acc[mt][nt][i] = 0.f;

    // ---- async prefetch of one 128x32 k-slab of all 4 matrices
    auto prefetch = [&](int kc, int stage) {
        const uint32_t stg = sbase + stage * STAGE_BYTES;
#pragma unroll
        for (int it = 0; it < 8; it++) {
            const int mat = it >> 1;                      // compile-time
            const int rem = ((it & 1) << 8) + tid;        // 0..511
            const int row = rem >> 2, chk = rem & 3;
            cp16(stg + mat * MAT_BYTES + row * ROW_STRIDE + chk * 16,
                 gbase[mat] + (long)row * 1024 + kc * 64 + chk * 16);
        }
    };

    auto compute = [&](int stage) {
        const uint32_t aHiB = sbase + stage * STAGE_BYTES;
        const uint32_t aLoB = aHiB + MAT_BYTES;
        const uint32_t bHiB = aHiB + 2 * MAT_BYTES;
        const uint32_t bLoB = aHiB + 3 * MAT_BYTES;
#pragma unroll
        for (int ks = 0; ks < 2; ks++) {
            uint32_t ah[2][4], al[2][4];
#pragma unroll
            for (int mt = 0; mt < 2; mt++) {
                const uint32_t off = (uint32_t)(warp_m * 32 + mt * 16 + qid) * ROW_STRIDE
                                   + ks * 32 + qtr * 4;
                ah[mt][0] = *(const uint32_t*)(smem + (aHiB - sbase) + off);
                ah[mt][1] = *(const uint32_t*)(smem + (aHiB - sbase) + off + 8 * ROW_STRIDE);
                ah[mt][2] = *(const uint32_t*)(smem + (aHiB - sbase) + off + 16);
                ah[mt][3] = *(const uint32_t*)(smem + (aHiB - sbase) + off + 8 * ROW_STRIDE + 16);
                al[mt][0] = *(const uint32_t*)(smem + (aLoB - sbase) + off);
                al[mt][1] = *(const uint32_t*)(smem + (aLoB - sbase) + off + 8 * ROW_STRIDE);
                al[mt][2] = *(const uint32_t*)(smem + (aLoB - sbase) + off + 16);
                al[mt][3] = *(const uint32_t*)(smem + (aLoB - sbase) + off + 8 * ROW_STRIDE + 16);
            }
#pragma unroll
            for (int nt = 0; nt < 8; nt++) {
                const uint32_t off = (uint32_t)(warp_n * 64 + nt * 8 + qid) * ROW_STRIDE
                                   + ks * 32 + qtr * 4;
                const uint32_t bh0 = *(const uint32_t*)(smem + (bHiB - sbase) + off);
                const uint32_t bh1 = *(const uint32_t*)(smem + (bHiB - sbase) + off + 16);
                const uint32_t bl0 = *(const uint32_t*)(smem + (bLoB - sbase) + off);
                const uint32_t bl1 = *(const uint32_t*)(smem + (bLoB - sbase) + off + 16);
#pragma unroll
                for (int mt = 0; mt < 2; mt++) {
                    MMA_BF16(acc[mt][nt], ah[mt], bh0, bh1);
                    MMA_BF16(acc[mt][nt], ah[mt], bl0, bl1);
                    MMA_BF16(acc[mt][nt], al[mt], bh0, bh1);
                }
            }
        }
    };

    prefetch(0, 0);
    CP_COMMIT();
    for (int kt = 0; kt < KITERS; kt++) {
        if (kt + 1 < KITERS) {
            prefetch(kt + 1, (kt + 1) & 1);
            CP_COMMIT();
            CP_WAIT1();
        } else {
            CP_WAIT0();
        }
        __syncthreads();
        compute(kt & 1);
        __syncthreads();
    }

    // ---- epilogue: +bias, direct float2 stores
    float* Cbase = (MODE == 0) ? g_gbuf : Cout;
#pragma unroll
    for (int mt = 0; mt < 2; mt++) {
        const int r0 = mtile * 128 + warp_m * 32 + mt * 16 + qid;
#pragma unroll
        for (int nt = 0; nt < 8; nt++) {
            const int col = ntile * 128 + warp_n * 64 + nt * 8 + qtr * 2;
            const float b0 = __ldg(&bias[col]), b1 = __ldg(&bias[col + 1]);
            float2 v0, v1;
            v0.x = acc[mt][nt][0] + b0; v0.y = acc[mt][nt][1] + b1;
            v1.x = acc[mt][nt][2] + b0; v1.y = acc[mt][nt][3] + b1;
            *(float2*)&Cbase[(long)r0 * 512 + col] = v0;
            *(float2*)&Cbase[(long)(r0 + 8) * 512 + col] = v1;
        }
    }
}

// ---------------------------------------------------------------- KNN + interp
// Writes relu(interp(g)) directly as row-major bf16 hi/lo (GEMM2's A).
__global__ __launch_bounds__(256) void knn_interp_relu_kernel(
    const float* __restrict__ xyz_dense, const float* __restrict__ xyz_sparse)
{
    __shared__ float sx[NPTS1], sy[NPTS1], sz[NPTS1];
    __shared__ float sw[128][3];
    __shared__ int   si[128][3];

    const int b  = blockIdx.y;
    const int p0 = blockIdx.x * 128;

    const float* xs = xyz_sparse + (long)b * NPTS1 * 3;
    for (int i = threadIdx.x; i < NPTS1; i += 256) {
        sx[i] = xs[i * 3 + 0];
        sy[i] = xs[i * 3 + 1];
        sz[i] = xs[i * 3 + 2];
    }
    __syncthreads();

    if (threadIdx.x < 128) {
        const int p = p0 + threadIdx.x;
        const float* xd = xyz_dense + ((long)b * NPTS2 + p) * 3;
        const float px = xd[0], py = xd[1], pz = xd[2];

        float d0 = 1e30f, d1 = 1e30f, d2 = 1e30f;
        int   i0 = 0, i1 = 0, i2 = 0;
#pragma unroll 4
        for (int j = 0; j < NPTS1; j++) {
            float dx = px - sx[j], dy = py - sy[j], dz = pz - sz[j];
            float d = dx * dx + dy * dy + dz * dz;
            if (d < d0)      { d2 = d1; i2 = i1; d1 = d0; i1 = i0; d0 = d; i0 = j; }
            else if (d < d1) { d2 = d1; i2 = i1; d1 = d;  i1 = j; }
            else if (d < d2) { d2 = d;  i2 = j; }
        }
        float w0 = 1.f / (sqrtf(d0) + EPSI);
        float w1 = 1.f / (sqrtf(d1) + EPSI);
        float w2 = 1.f / (sqrtf(d2) + EPSI);
        const float inv = 1.f / (w0 + w1 + w2);
        sw[threadIdx.x][0] = w0 * inv;
        sw[threadIdx.x][1] = w1 * inv;
        sw[threadIdx.x][2] = w2 * inv;
        si[threadIdx.x][0] = i0;
        si[threadIdx.x][1] = i1;
        si[threadIdx.x][2] = i2;
    }
    __syncthreads();

    const float* g = g_gbuf + (long)b * NPTS1 * CF;
    const long mBase = (long)b * NPTS2 + p0;

    for (int e = threadIdx.x; e < 128 * 64; e += 256) {
        const int p = e >> 6;       // point within block
        const int j = e & 63;       // 8-channel chunk
        const float w0 = sw[p][0], w1 = sw[p][1], w2 = sw[p][2];
        const float* r0 = g + (long)si[p][0] * CF + j * 8;
        const float* r1 = g + (long)si[p][1] * CF + j * 8;
        const float* r2 = g + (long)si[p][2] * CF + j * 8;
        float4 a0 = *(const float4*)r0, a1 = *(const float4*)(r0 + 4);
        float4 b0 = *(const float4*)r1, b1 = *(const float4*)(r1 + 4);
        float4 c0 = *(const float4*)r2, c1 = *(const float4*)(r2 + 4);

        float v[8];
        v[0] = w0 * a0.x + w1 * b0.x + w2 * c0.x;
        v[1] = w0 * a0.y + w1 * b0.y + w2 * c0.y;
        v[2] = w0 * a0.z + w1 * b0.z + w2 * c0.z;
        v[3] = w0 * a0.w + w1 * b0.w + w2 * c0.w;
        v[4] = w0 * a1.x + w1 * b1.x + w2 * c1.x;
        v[5] = w0 * a1.y + w1 * b1.y + w2 * c1.y;
        v[6] = w0 * a1.z + w1 * b1.z + w2 * c1.z;
        v[7] = w0 * a1.w + w1 * b1.w + w2 * c1.w;

        union { __nv_bfloat16 h[8]; uint4 u; } H, L;
#pragma unroll
        for (int k = 0; k < 8; k++) {
            float vr = fmaxf(v[k], 0.f);
            H.h[k] = __float2bfloat16(vr);
            L.h[k] = __float2bfloat16(vr - __bfloat162float(H.h[k]));
        }
        const long off = (mBase + p) * CF + j * 8;
        *(uint4*)(g_a2_hi + off) = H.u;
        *(uint4*)(g_a2_lo + off) = L.u;
    }
}

// ---------------------------------------------------------------- launch
extern "C" void kernel_launch(void* const* d_in, const int* in_sizes, int n_in,
                              void* d_out, int out_size)
{
    const float* xyz_dense  = (const float*)d_in[0];  // (16, 4096, 3)
    const float* xyz_sparse = (const float*)d_in[1];  // (16, 1024, 3)
    const float* feat       = (const float*)d_in[2];  // (16, 1024, 512)
    const float* W1         = (const float*)d_in[3];  // (512, 512)
    const float* b1         = (const float*)d_in[4];  // (512)
    const float* W2         = (const float*)d_in[5];  // (512, 512)
    const float* b2         = (const float*)d_in[6];  // (512)
    float* out = (float*)d_out;                       // (16, 4096, 512)

    static bool attr_done = false;
    if (!attr_done) {
        cudaFuncSetAttribute(mma_gemm_kernel<0>,
            cudaFuncAttributeMaxDynamicSharedMemorySize, SMEM_GEMM);
        cudaFuncSetAttribute(mma_gemm_kernel<1>,
            cudaFuncAttributeMaxDynamicSharedMemorySize, SMEM_GEMM);
        attr_done = true;
    }

    // 0) fp32 -> bf16 hi/lo conversions (row-major)
    convert_split_kernel<0><<<(16384 * 64) / 256, 256>>>(feat);
    convert_split_kernel<1><<<(512 * 64) / 256, 256>>>(W1);
    convert_split_kernel<2><<<(512 * 64) / 256, 256>>>(W2);

    // 1) g = feat @ W1^T + b1  (interp is linear: do GEMM on sparse side)
    {
        dim3 grid(4, MTILES1);
        mma_gemm_kernel<0><<<grid, 256, SMEM_GEMM>>>(b1, nullptr);
    }

    // 2) a2 = relu(interp3(g))  -> row-major bf16 hi/lo
    {
        dim3 grid(NPTS2 / 128, BB);
        knn_interp_relu_kernel<<<grid, 256>>>(xyz_dense, xyz_sparse);
    }

    // 3) out = a2 @ W2^T + b2
    {
        dim3 grid(4, MTILES2);
        mma_gemm_kernel<1><<<grid, 256, SMEM_GEMM>>>(b2, out);
    }
}